// round 8
// baseline (speedup 1.0000x reference)
#include <cuda_runtime.h>
#include <cuda_bf16.h>
#include <cstdint>
#include <cmath>

#define I_DIM 512
#define H_DIM 512
#define KTOT  1024
#define NTOT  1024
#define BATCH 65536

// ---------------------------------------------------------------------------
// Device scratch
// A2: u4 index = ((rb*64 + kb)*2 + term)*32 + lane   rb: 16-row block, kb: k16 block
// W2: u4 index = ((nb*64 + kb)*2 + term)*32 + lane   nb: 16-col block (INTERLEAVED:
//     packed col c -> j = c>>1 ; c even = tau logits, c odd = f pre-activations)
// ---------------------------------------------------------------------------
__device__ uint4  g_A2[(size_t)4096 * 64 * 2 * 32];      // 256 MB
__device__ uint4  g_W2[(size_t)64 * 64 * 2 * 32];        // 4 MB
__device__ float  g_Y[(size_t)BATCH * H_DIM];            // 128 MB (pre-LN y)
__device__ float2 g_Spart[(size_t)BATCH * 32];           // 16 MB  (LN partials)

__device__ __forceinline__ uint32_t smem_u32(const void* p) {
    uint32_t a;
    asm("{ .reg .u64 t; cvta.to.shared.u64 t, %1; cvt.u32.u64 %0, t; }"
        : "=r"(a) : "l"(p));
    return a;
}
__device__ __forceinline__ uint32_t pack_bf2(float a, float b) {
    __nv_bfloat16 ha = __float2bfloat16(a);
    __nv_bfloat16 hb = __float2bfloat16(b);
    return (uint32_t)__bfloat16_as_ushort(ha) |
           ((uint32_t)__bfloat16_as_ushort(hb) << 16);
}
__device__ __forceinline__ float bf_hi(float v) {
    return __bfloat162float(__float2bfloat16(v));
}
__device__ __forceinline__ void mma16816(float* c, const uint4& a,
                                         uint32_t b0, uint32_t b1) {
    asm volatile(
        "mma.sync.aligned.m16n8k16.row.col.f32.bf16.bf16.f32 "
        "{%0,%1,%2,%3}, {%4,%5,%6,%7}, {%8,%9}, {%0,%1,%2,%3};"
        : "+f"(c[0]), "+f"(c[1]), "+f"(c[2]), "+f"(c[3])
        : "r"(a.x), "r"(a.y), "r"(a.z), "r"(a.w), "r"(b0), "r"(b1));
}
#define CP_ASYNC16(dst, src) \
    asm volatile("cp.async.cg.shared.global [%0], [%1], 16;" \
                 :: "r"(dst), "l"(src) : "memory")
#define CP_COMMIT() asm volatile("cp.async.commit_group;" ::: "memory")
#define CP_WAIT1()  asm volatile("cp.async.wait_group 1;" ::: "memory")

// ---------------------------------------------------------------------------
// Pack W into fragment-linear hi/lo bf16 tiles, with (tau,f) column interleave.
// packed col c: j = c>>1 ; c even -> W_tau[j][k]
//                          c odd  -> k<512 ? W_in[j][k] : W_rec[j][k-512]
// ---------------------------------------------------------------------------
__device__ __forceinline__ float w_at2(const float* W_in, const float* W_rec,
                                       const float* W_tau, int c, int k) {
    int j = c >> 1;
    if ((c & 1) == 0) return W_tau[j * KTOT + k];
    return (k < I_DIM) ? W_in[j * I_DIM + k] : W_rec[j * H_DIM + (k - I_DIM)];
}

__global__ void pack_w_kernel(const float* __restrict__ W_in,
                              const float* __restrict__ W_rec,
                              const float* __restrict__ W_tau) {
    int t = blockIdx.x * blockDim.x + threadIdx.x;
    int lane = t & 31;
    int idx = t >> 5;
    int kb = idx & 63;
    int nb = idx >> 6;

    int n0 = nb * 16 + (lane >> 2);
    int k0 = kb * 16 + (lane & 3) * 2;

    float v[8];
    v[0] = w_at2(W_in, W_rec, W_tau, n0,     k0);
    v[1] = w_at2(W_in, W_rec, W_tau, n0,     k0 + 1);
    v[2] = w_at2(W_in, W_rec, W_tau, n0,     k0 + 8);
    v[3] = w_at2(W_in, W_rec, W_tau, n0,     k0 + 9);
    v[4] = w_at2(W_in, W_rec, W_tau, n0 + 8, k0);
    v[5] = w_at2(W_in, W_rec, W_tau, n0 + 8, k0 + 1);
    v[6] = w_at2(W_in, W_rec, W_tau, n0 + 8, k0 + 8);
    v[7] = w_at2(W_in, W_rec, W_tau, n0 + 8, k0 + 9);

    uint4 hi, lo;
    hi.x = pack_bf2(v[0], v[1]); hi.y = pack_bf2(v[2], v[3]);
    hi.z = pack_bf2(v[4], v[5]); hi.w = pack_bf2(v[6], v[7]);
    lo.x = pack_bf2(v[0] - bf_hi(v[0]), v[1] - bf_hi(v[1]));
    lo.y = pack_bf2(v[2] - bf_hi(v[2]), v[3] - bf_hi(v[3]));
    lo.z = pack_bf2(v[4] - bf_hi(v[4]), v[5] - bf_hi(v[5]));
    lo.w = pack_bf2(v[6] - bf_hi(v[6]), v[7] - bf_hi(v[7]));

    size_t base = ((size_t)(nb * 64 + kb) * 2) * 32 + lane;
    g_W2[base]      = hi;
    g_W2[base + 32] = lo;
}

// ---------------------------------------------------------------------------
// Split A = [x | h] into fragment-linear hi/lo bf16 tiles.
// ---------------------------------------------------------------------------
__global__ __launch_bounds__(256)
void split_a_kernel(const float* __restrict__ x, const float* __restrict__ h) {
    const int rb = blockIdx.x;            // 0..4095
    const int tid = threadIdx.x;
    const int wid = tid >> 5;
    const int lane = tid & 31;

    const int r0 = lane >> 2;
    const int cq = (lane & 3) * 2;
    const size_t rowA = (size_t)rb * 16 + r0;
    const size_t rowB = rowA + 8;

#pragma unroll
    for (int j = 0; j < 8; j++) {
        int kb = wid * 8 + j;             // 0..63
        int kg = kb * 16 + cq;
        const float* srcA;
        const float* srcB;
        if (kb < 32) { srcA = x + rowA * I_DIM + kg;          srcB = x + rowB * I_DIM + kg; }
        else         { srcA = h + rowA * H_DIM + (kg - 512);  srcB = h + rowB * H_DIM + (kg - 512); }

        float a0 = srcA[0], a1 = srcA[1], a2 = srcA[8], a3 = srcA[9];
        float b0 = srcB[0], b1 = srcB[1], b2 = srcB[8], b3 = srcB[9];

        uint4 hi, lo;
        hi.x = pack_bf2(a0, a1); hi.y = pack_bf2(b0, b1);
        hi.z = pack_bf2(a2, a3); hi.w = pack_bf2(b2, b3);
        lo.x = pack_bf2(a0 - bf_hi(a0), a1 - bf_hi(a1));
        lo.y = pack_bf2(b0 - bf_hi(b0), b1 - bf_hi(b1));
        lo.z = pack_bf2(a2 - bf_hi(a2), a3 - bf_hi(a3));
        lo.w = pack_bf2(b2 - bf_hi(b2), b3 - bf_hi(b3));

        size_t base = ((size_t)(rb * 64 + kb) * 2) * 32 + lane;
        g_A2[base]      = hi;
        g_A2[base + 32] = lo;
    }
}

// ---------------------------------------------------------------------------
// GEMM + fused pointwise epilogue.
// CTA tile 128x128, warp tile 64x32 (2x4 warps), BK=32, 3-stage cp.async.
// Tail: each C-frag float pair = (tau_pre, f_pre) for one j -> compute tau, y;
// write out_tau, g_Y, and per-(row,bn,wn) LayerNorm partials (deterministic).
// ---------------------------------------------------------------------------
#define STAGE_BYTES 32768
#define N_STAGES 3

__global__ __launch_bounds__(256)
void gemm_mma_kernel(const float* __restrict__ hin,
                     const float* __restrict__ b_in,
                     const float* __restrict__ b_tau,
                     float* __restrict__ out_tau) {
    extern __shared__ char smem[];
    const uint32_t sbase = smem_u32(smem);

    const int tid  = threadIdx.x;
    const int wid  = tid >> 5;
    const int lane = tid & 31;
    const int bn = blockIdx.x;            // 0..7
    const int bm = blockIdx.y;            // 0..511
    const int wm = wid & 1;
    const int wn = wid >> 1;

    uint32_t soff[8];
    const uint4* gptr[8];
#pragma unroll
    for (int j = 0; j < 8; j++) {
        int c = tid + j * 256;            // chunk id 0..2047
        int cl   = c & 31;
        int blk  = (c >> 5) & 7;
        int term = (c >> 8) & 1;
        int kb   = (c >> 9) & 1;
        if (c < 1024) {
            int rb = bm * 8 + blk;
            gptr[j] = g_A2 + (((size_t)(rb * 64 + kb) * 2 + term) * 32 + cl);
        } else {
            int nb = bn * 8 + blk;
            gptr[j] = g_W2 + (((size_t)(nb * 64 + kb) * 2 + term) * 32 + cl);
        }
        soff[j] = (uint32_t)(c * 16);
    }

    float acc[4][4][4];
#pragma unroll
    for (int a = 0; a < 4; a++)
#pragma unroll
        for (int b = 0; b < 4; b++)
#pragma unroll
            for (int d = 0; d < 4; d++) acc[a][b][d] = 0.f;

#pragma unroll
    for (int s = 0; s < 2; s++) {
#pragma unroll
        for (int j = 0; j < 8; j++)
            CP_ASYNC16(sbase + s * STAGE_BYTES + soff[j], gptr[j] + (size_t)s * 128);
        CP_COMMIT();
    }

    const int mbB = wm * 4;
    const int nbB = wn * 2;

    for (int i = 0; i < 32; i++) {
        CP_WAIT1();
        __syncthreads();

        if (i + 2 < 32) {
            uint32_t sb = sbase + ((i + 2) % N_STAGES) * STAGE_BYTES;
#pragma unroll
            for (int j = 0; j < 8; j++)
                CP_ASYNC16(sb + soff[j], gptr[j] + (size_t)(i + 2) * 128);
        }
        CP_COMMIT();

        const uint32_t st = sbase + (i % N_STAGES) * STAGE_BYTES;
#pragma unroll
        for (int kb = 0; kb < 2; kb++) {
            uint4 ah[4], al[4], bh[2], bl[2];
#pragma unroll
            for (int mb = 0; mb < 4; mb++) {
                uint32_t ahi = st + ((kb * 2 + 0) * 8 + mbB + mb) * 512 + lane * 16;
                uint32_t alo = st + ((kb * 2 + 1) * 8 + mbB + mb) * 512 + lane * 16;
                asm volatile("ld.shared.v4.u32 {%0,%1,%2,%3}, [%4];"
                    : "=r"(ah[mb].x), "=r"(ah[mb].y), "=r"(ah[mb].z), "=r"(ah[mb].w) : "r"(ahi));
                asm volatile("ld.shared.v4.u32 {%0,%1,%2,%3}, [%4];"
                    : "=r"(al[mb].x), "=r"(al[mb].y), "=r"(al[mb].z), "=r"(al[mb].w) : "r"(alo));
            }
#pragma unroll
            for (int p = 0; p < 2; p++) {
                uint32_t bhi = st + 16384 + ((kb * 2 + 0) * 8 + nbB + p) * 512 + lane * 16;
                uint32_t blo = st + 16384 + ((kb * 2 + 1) * 8 + nbB + p) * 512 + lane * 16;
                asm volatile("ld.shared.v4.u32 {%0,%1,%2,%3}, [%4];"
                    : "=r"(bh[p].x), "=r"(bh[p].y), "=r"(bh[p].z), "=r"(bh[p].w) : "r"(bhi));
                asm volatile("ld.shared.v4.u32 {%0,%1,%2,%3}, [%4];"
                    : "=r"(bl[p].x), "=r"(bl[p].y), "=r"(bl[p].z), "=r"(bl[p].w) : "r"(blo));
            }
#pragma unroll
            for (int term = 0; term < 3; term++) {
#pragma unroll
                for (int mt = 0; mt < 4; mt++) {
#pragma unroll
                    for (int nt = 0; nt < 4; nt++) {
                        const uint4& A = (term == 2) ? al[mt] : ah[mt];
                        const uint4& B = (term == 1) ? bl[nt >> 1] : bh[nt >> 1];
                        uint32_t b0 = (nt & 1) ? B.z : B.x;
                        uint32_t b1 = (nt & 1) ? B.w : B.y;
                        mma16816(acc[mt][nt], A, b0, b1);
                    }
                }
            }
        }
        // bottom barrier removed: top wait+sync of next iter orders the
        // stage reuse (stage written at iter i was last read at iter i-1).
    }

    // ---- fused pointwise epilogue ----
    const int g  = lane >> 2;
    const int tg = lane & 3;
    const int jb0 = bn * 64 + wn * 16 + tg;   // j = jb0 + nt*4

#pragma unroll
    for (int mt = 0; mt < 4; mt++) {
        int row0 = bm * 128 + wm * 64 + mt * 16 + g;
        int row1 = row0 + 8;
        float s0 = 0.f, q0 = 0.f, s1 = 0.f, q1 = 0.f;
#pragma unroll
        for (int nt = 0; nt < 4; nt++) {
            int j = jb0 + nt * 4;
            float btu = __ldg(&b_tau[j]);
            float bin = __ldg(&b_in[j]);
            {
                float tau = 0.5f + 4.5f / (1.0f + __expf(-(acc[mt][nt][0] + btu)));
                float f   = tanhf(acc[mt][nt][1] + bin);
                float hv  = hin[(size_t)row0 * H_DIM + j];
                float yv  = hv + 0.1f * (f - hv) / tau;
                out_tau[(size_t)row0 * H_DIM + j] = tau;
                g_Y[(size_t)row0 * H_DIM + j] = yv;
                s0 += yv; q0 += yv * yv;
            }
            {
                float tau = 0.5f + 4.5f / (1.0f + __expf(-(acc[mt][nt][2] + btu)));
                float f   = tanhf(acc[mt][nt][3] + bin);
                float hv  = hin[(size_t)row1 * H_DIM + j];
                float yv  = hv + 0.1f * (f - hv) / tau;
                out_tau[(size_t)row1 * H_DIM + j] = tau;
                g_Y[(size_t)row1 * H_DIM + j] = yv;
                s1 += yv; q1 += yv * yv;
            }
        }
        // reduce across the quad (tg = 0..3 are lanes xor 1,2)
        s0 += __shfl_xor_sync(0xffffffffu, s0, 1);
        s0 += __shfl_xor_sync(0xffffffffu, s0, 2);
        q0 += __shfl_xor_sync(0xffffffffu, q0, 1);
        q0 += __shfl_xor_sync(0xffffffffu, q0, 2);
        s1 += __shfl_xor_sync(0xffffffffu, s1, 1);
        s1 += __shfl_xor_sync(0xffffffffu, s1, 2);
        q1 += __shfl_xor_sync(0xffffffffu, q1, 1);
        q1 += __shfl_xor_sync(0xffffffffu, q1, 2);
        if (tg == 0) {
            g_Spart[(size_t)row0 * 32 + bn * 4 + wn] = make_float2(s0, q0);
            g_Spart[(size_t)row1 * 32 + bn * 4 + wn] = make_float2(s1, q1);
        }
    }
}

// ---------------------------------------------------------------------------
// Finalize: per row, reduce 32 LN partials, normalize y -> out_h.
// 2 rows per 256-thread block.
// ---------------------------------------------------------------------------
__global__ __launch_bounds__(256)
void finalize_kernel(const float* __restrict__ gamma, const float* __restrict__ beta,
                     float* __restrict__ out_h) {
    const int tid = threadIdx.x;
    const int r   = tid >> 7;
    const int t   = tid & 127;
    const size_t row = (size_t)blockIdx.x * 2 + r;
    const int w = tid >> 5;

    __shared__ float2 mv[2];
    if (w == 0 || w == 4) {
        size_t rr = (size_t)blockIdx.x * 2 + (w >> 2);
        float2 p = g_Spart[rr * 32 + (tid & 31)];
        float s = p.x, q = p.y;
#pragma unroll
        for (int off = 16; off > 0; off >>= 1) {
            s += __shfl_xor_sync(0xffffffffu, s, off);
            q += __shfl_xor_sync(0xffffffffu, q, off);
        }
        if ((tid & 31) == 0) {
            float mu  = s * (1.0f / H_DIM);
            float var = q * (1.0f / H_DIM) - mu * mu;
            mv[w >> 2] = make_float2(mu, rsqrtf(var + 1e-5f));
        }
    }
    __syncthreads();

    float mu  = mv[r].x;
    float inv = mv[r].y;

    float4 y4 = *((const float4*)(g_Y + row * H_DIM) + t);
    float4 g4 = ((const float4*)gamma)[t];
    float4 b4 = ((const float4*)beta)[t];
    float4 oh;
    oh.x = (y4.x - mu) * inv * g4.x + b4.x;
    oh.y = (y4.y - mu) * inv * g4.y + b4.y;
    oh.z = (y4.z - mu) * inv * g4.z + b4.z;
    oh.w = (y4.w - mu) * inv * g4.w + b4.w;
    *((float4*)(out_h + row * H_DIM) + t) = oh;
}

// ---------------------------------------------------------------------------
extern "C" void kernel_launch(void* const* d_in, const int* in_sizes, int n_in,
                              void* d_out, int out_size) {
    const float* x     = (const float*)d_in[0];
    const float* h     = (const float*)d_in[1];
    const float* W_in  = (const float*)d_in[2];
    const float* b_in  = (const float*)d_in[3];
    const float* W_rec = (const float*)d_in[4];
    const float* W_tau = (const float*)d_in[5];
    const float* b_tau = (const float*)d_in[6];
    const float* gamma = (const float*)d_in[7];
    const float* beta  = (const float*)d_in[8];

    const int B = in_sizes[0] / I_DIM;    // 65536

    float* out = (float*)d_out;
    float* out_h   = out;
    float* out_tau = out + (size_t)B * H_DIM;

    pack_w_kernel<<<512, 256>>>(W_in, W_rec, W_tau);
    split_a_kernel<<<B / 16, 256>>>(x, h);

    cudaFuncSetAttribute(gemm_mma_kernel,
                         cudaFuncAttributeMaxDynamicSharedMemorySize,
                         N_STAGES * STAGE_BYTES);
    dim3 ggrid(NTOT / 128, B / 128);      // (8, 512)
    gemm_mma_kernel<<<ggrid, 256, N_STAGES * STAGE_BYTES>>>(h, b_in, b_tau, out_tau);

    finalize_kernel<<<B / 2, 256>>>(gamma, beta, out_h);
}

// round 10
// speedup vs baseline: 1.0297x; 1.0297x over previous
#include <cuda_runtime.h>
#include <cuda_bf16.h>
#include <cstdint>
#include <cmath>

#define I_DIM 512
#define H_DIM 512
#define KTOT  1024
#define NTOT  1024
#define BATCH 65536

// ---------------------------------------------------------------------------
// Device scratch
// A2: u4 index = ((rb*64 + kb)*2 + term)*32 + lane
// W2: u4 index = ((nb*64 + kb)*2 + term)*32 + lane  (cols interleaved: 2j=tau, 2j+1=f)
// ---------------------------------------------------------------------------
__device__ uint4  g_A2[(size_t)4096 * 64 * 2 * 32];      // 256 MB
__device__ uint4  g_W2[(size_t)64 * 64 * 2 * 32];        // 4 MB
__device__ float  g_Y[(size_t)BATCH * H_DIM];            // 128 MB (pre-LN y)
__device__ float2 g_Spart[(size_t)BATCH * 8];            // 4 MB (LN partials, per bn)

__device__ __forceinline__ uint32_t smem_u32(const void* p) {
    uint32_t a;
    asm("{ .reg .u64 t; cvta.to.shared.u64 t, %1; cvt.u32.u64 %0, t; }"
        : "=r"(a) : "l"(p));
    return a;
}
__device__ __forceinline__ uint32_t pack_bf2(float a, float b) {
    __nv_bfloat16 ha = __float2bfloat16(a);
    __nv_bfloat16 hb = __float2bfloat16(b);
    return (uint32_t)__bfloat16_as_ushort(ha) |
           ((uint32_t)__bfloat16_as_ushort(hb) << 16);
}
__device__ __forceinline__ float bf_hi(float v) {
    return __bfloat162float(__float2bfloat16(v));
}
__device__ __forceinline__ void mma16816(float* c, const uint4& a,
                                         uint32_t b0, uint32_t b1) {
    asm volatile(
        "mma.sync.aligned.m16n8k16.row.col.f32.bf16.bf16.f32 "
        "{%0,%1,%2,%3}, {%4,%5,%6,%7}, {%8,%9}, {%0,%1,%2,%3};"
        : "+f"(c[0]), "+f"(c[1]), "+f"(c[2]), "+f"(c[3])
        : "r"(a.x), "r"(a.y), "r"(a.z), "r"(a.w), "r"(b0), "r"(b1));
}
#define CP_ASYNC16(dst, src) \
    asm volatile("cp.async.cg.shared.global [%0], [%1], 16;" \
                 :: "r"(dst), "l"(src) : "memory")
#define CP_COMMIT() asm volatile("cp.async.commit_group;" ::: "memory")
#define CP_WAIT1()  asm volatile("cp.async.wait_group 1;" ::: "memory")
#define CP_WAIT0()  asm volatile("cp.async.wait_group 0;" ::: "memory")
#define LDS128(v, addr) \
    asm volatile("ld.shared.v4.u32 {%0,%1,%2,%3}, [%4];" \
        : "=r"((v).x), "=r"((v).y), "=r"((v).z), "=r"((v).w) : "r"(addr))

// ---------------------------------------------------------------------------
// Pack W (interleaved columns: packed col c -> j=c>>1; even=tau, odd=f).
// ---------------------------------------------------------------------------
__device__ __forceinline__ float w_at2(const float* W_in, const float* W_rec,
                                       const float* W_tau, int c, int k) {
    int j = c >> 1;
    if ((c & 1) == 0) return W_tau[j * KTOT + k];
    return (k < I_DIM) ? W_in[j * I_DIM + k] : W_rec[j * H_DIM + (k - I_DIM)];
}

__global__ void pack_w_kernel(const float* __restrict__ W_in,
                              const float* __restrict__ W_rec,
                              const float* __restrict__ W_tau) {
    int t = blockIdx.x * blockDim.x + threadIdx.x;
    int lane = t & 31;
    int idx = t >> 5;
    int kb = idx & 63;
    int nb = idx >> 6;

    int n0 = nb * 16 + (lane >> 2);
    int k0 = kb * 16 + (lane & 3) * 2;

    float v[8];
    v[0] = w_at2(W_in, W_rec, W_tau, n0,     k0);
    v[1] = w_at2(W_in, W_rec, W_tau, n0,     k0 + 1);
    v[2] = w_at2(W_in, W_rec, W_tau, n0,     k0 + 8);
    v[3] = w_at2(W_in, W_rec, W_tau, n0,     k0 + 9);
    v[4] = w_at2(W_in, W_rec, W_tau, n0 + 8, k0);
    v[5] = w_at2(W_in, W_rec, W_tau, n0 + 8, k0 + 1);
    v[6] = w_at2(W_in, W_rec, W_tau, n0 + 8, k0 + 8);
    v[7] = w_at2(W_in, W_rec, W_tau, n0 + 8, k0 + 9);

    uint4 hi, lo;
    hi.x = pack_bf2(v[0], v[1]); hi.y = pack_bf2(v[2], v[3]);
    hi.z = pack_bf2(v[4], v[5]); hi.w = pack_bf2(v[6], v[7]);
    lo.x = pack_bf2(v[0] - bf_hi(v[0]), v[1] - bf_hi(v[1]));
    lo.y = pack_bf2(v[2] - bf_hi(v[2]), v[3] - bf_hi(v[3]));
    lo.z = pack_bf2(v[4] - bf_hi(v[4]), v[5] - bf_hi(v[5]));
    lo.w = pack_bf2(v[6] - bf_hi(v[6]), v[7] - bf_hi(v[7]));

    size_t base = ((size_t)(nb * 64 + kb) * 2) * 32 + lane;
    g_W2[base]      = hi;
    g_W2[base + 32] = lo;
}

// ---------------------------------------------------------------------------
// Split A = [x | h] into fragment-linear hi/lo bf16 tiles.
// ---------------------------------------------------------------------------
__global__ __launch_bounds__(256)
void split_a_kernel(const float* __restrict__ x, const float* __restrict__ h) {
    const int rb = blockIdx.x;
    const int tid = threadIdx.x;
    const int wid = tid >> 5;
    const int lane = tid & 31;

    const int r0 = lane >> 2;
    const int cq = (lane & 3) * 2;
    const size_t rowA = (size_t)rb * 16 + r0;
    const size_t rowB = rowA + 8;

#pragma unroll
    for (int j = 0; j < 8; j++) {
        int kb = wid * 8 + j;
        int kg = kb * 16 + cq;
        const float* srcA;
        const float* srcB;
        if (kb < 32) { srcA = x + rowA * I_DIM + kg;          srcB = x + rowB * I_DIM + kg; }
        else         { srcA = h + rowA * H_DIM + (kg - 512);  srcB = h + rowB * H_DIM + (kg - 512); }

        float a0 = srcA[0], a1 = srcA[1], a2 = srcA[8], a3 = srcA[9];
        float b0 = srcB[0], b1 = srcB[1], b2 = srcB[8], b3 = srcB[9];

        uint4 hi, lo;
        hi.x = pack_bf2(a0, a1); hi.y = pack_bf2(b0, b1);
        hi.z = pack_bf2(a2, a3); hi.w = pack_bf2(b2, b3);
        lo.x = pack_bf2(a0 - bf_hi(a0), a1 - bf_hi(a1));
        lo.y = pack_bf2(b0 - bf_hi(b0), b1 - bf_hi(b1));
        lo.z = pack_bf2(a2 - bf_hi(a2), a3 - bf_hi(a3));
        lo.w = pack_bf2(b2 - bf_hi(b2), b3 - bf_hi(b3));

        size_t base = ((size_t)(rb * 64 + kb) * 2) * 32 + lane;
        g_A2[base]      = hi;
        g_A2[base + 32] = lo;
    }
}

// ---------------------------------------------------------------------------
// GEMM + smem-staged fused epilogue.
// Mainloop identical to R6 (128x128 CTA, 64x32 warp, 3-stage cp.async).
// Tail: acc -> smem tiles (tau_pre, f_pre) -> coalesced writeout with biases,
// sigmoid/tanh, y, out_tau, g_Y, LN partials per (row, bn).
// smem tail layout: tauT [128][68]f @0, fT [128][68]f @34816. (68*4=272B rows,
// 16B-aligned for LDS128; banks conflict-free: (tg+4g) mod 32 is a bijection.)
// ---------------------------------------------------------------------------
#define STAGE_BYTES 32768
#define N_STAGES 3
#define TPAD 68

__global__ __launch_bounds__(256)
void gemm_mma_kernel(const float* __restrict__ hin,
                     const float* __restrict__ b_in,
                     const float* __restrict__ b_tau,
                     float* __restrict__ out_tau) {
    extern __shared__ char smem[];
    const uint32_t sbase = smem_u32(smem);

    const int tid  = threadIdx.x;
    const int wid  = tid >> 5;
    const int lane = tid & 31;
    const int bn = blockIdx.x;            // 0..7
    const int bm = blockIdx.y;            // 0..511
    const int wm = wid & 1;
    const int wn = wid >> 1;

    uint32_t soff[8];
    const uint4* gptr[8];
#pragma unroll
    for (int j = 0; j < 8; j++) {
        int c = tid + j * 256;
        int cl   = c & 31;
        int blk  = (c >> 5) & 7;
        int term = (c >> 8) & 1;
        int kb   = (c >> 9) & 1;
        if (c < 1024) {
            int rb = bm * 8 + blk;
            gptr[j] = g_A2 + (((size_t)(rb * 64 + kb) * 2 + term) * 32 + cl);
        } else {
            int nb = bn * 8 + blk;
            gptr[j] = g_W2 + (((size_t)(nb * 64 + kb) * 2 + term) * 32 + cl);
        }
        soff[j] = (uint32_t)(c * 16);
    }

    float acc[4][4][4];
#pragma unroll
    for (int a = 0; a < 4; a++)
#pragma unroll
        for (int b = 0; b < 4; b++)
#pragma unroll
            for (int d = 0; d < 4; d++) acc[a][b][d] = 0.f;

#pragma unroll
    for (int s = 0; s < 2; s++) {
#pragma unroll
        for (int j = 0; j < 8; j++)
            CP_ASYNC16(sbase + s * STAGE_BYTES + soff[j], gptr[j] + (size_t)s * 128);
        CP_COMMIT();
    }

    const int mbB = wm * 4;
    const int nbB = wn * 2;

    for (int i = 0; i < 32; i++) {
        CP_WAIT1();
        __syncthreads();

        if (i + 2 < 32) {
            uint32_t sb = sbase + ((i + 2) % N_STAGES) * STAGE_BYTES;
#pragma unroll
            for (int j = 0; j < 8; j++)
                CP_ASYNC16(sb + soff[j], gptr[j] + (size_t)(i + 2) * 128);
        }
        CP_COMMIT();

        const uint32_t st = sbase + (i % N_STAGES) * STAGE_BYTES;
#pragma unroll
        for (int kb = 0; kb < 2; kb++) {
            uint4 ah[4], al[4], bh[2], bl[2];
#pragma unroll
            for (int mb = 0; mb < 4; mb++) {
                uint32_t ahi = st + ((kb * 2 + 0) * 8 + mbB + mb) * 512 + lane * 16;
                uint32_t alo = st + ((kb * 2 + 1) * 8 + mbB + mb) * 512 + lane * 16;
                LDS128(ah[mb], ahi);
                LDS128(al[mb], alo);
            }
#pragma unroll
            for (int p = 0; p < 2; p++) {
                uint32_t bhi = st + 16384 + ((kb * 2 + 0) * 8 + nbB + p) * 512 + lane * 16;
                uint32_t blo = st + 16384 + ((kb * 2 + 1) * 8 + nbB + p) * 512 + lane * 16;
                LDS128(bh[p], bhi);
                LDS128(bl[p], blo);
            }
#pragma unroll
            for (int term = 0; term < 3; term++) {
#pragma unroll
                for (int mt = 0; mt < 4; mt++) {
#pragma unroll
                    for (int nt = 0; nt < 4; nt++) {
                        const uint4& A = (term == 2) ? al[mt] : ah[mt];
                        const uint4& B = (term == 1) ? bl[nt >> 1] : bh[nt >> 1];
                        uint32_t b0 = (nt & 1) ? B.z : B.x;
                        uint32_t b1 = (nt & 1) ? B.w : B.y;
                        mma16816(acc[mt][nt], A, b0, b1);
                    }
                }
            }
        }
    }

    // ---- tail: drain pipeline, then reuse smem for staging ----
    CP_WAIT0();
    __syncthreads();

    const uint32_t tauT = sbase;                  // [128][68] float
    const uint32_t fT   = sbase + 128 * TPAD * 4; // [128][68] float
    const int g  = lane >> 2;
    const int tg = lane & 3;

    // Phase 1: scatter raw pre-activations to smem
#pragma unroll
    for (int mt = 0; mt < 4; mt++) {
        int r0 = wm * 64 + mt * 16 + g;
        int r1 = r0 + 8;
#pragma unroll
        for (int nt = 0; nt < 4; nt++) {
            int jj = wn * 16 + nt * 4 + tg;
            asm volatile("st.shared.f32 [%0], %1;" :: "r"(tauT + (uint32_t)(r0 * TPAD + jj) * 4), "f"(acc[mt][nt][0]) : "memory");
            asm volatile("st.shared.f32 [%0], %1;" :: "r"(fT   + (uint32_t)(r0 * TPAD + jj) * 4), "f"(acc[mt][nt][1]) : "memory");
            asm volatile("st.shared.f32 [%0], %1;" :: "r"(tauT + (uint32_t)(r1 * TPAD + jj) * 4), "f"(acc[mt][nt][2]) : "memory");
            asm volatile("st.shared.f32 [%0], %1;" :: "r"(fT   + (uint32_t)(r1 * TPAD + jj) * 4), "f"(acc[mt][nt][3]) : "memory");
        }
    }
    __syncthreads();

    // Phase 2: coalesced writeout. Half-warp (16 lanes) owns a row per iter.
    const int jj4 = tid & 15;                     // float4 index within row (0..15)
    const int rgrp = tid >> 4;                    // 0..15
    const int jbase = bn * 64;
    const float4 bt4 = ((const float4*)b_tau)[jbase / 4 + jj4];
    const float4 bi4 = ((const float4*)b_in)[jbase / 4 + jj4];

#pragma unroll
    for (int it = 0; it < 8; it++) {
        int r = rgrp + it * 16;                   // 0..127
        size_t row = (size_t)bm * 128 + r;

        float4 tp, fp;
        LDS128(*(uint4*)&tp, tauT + (uint32_t)(r * TPAD + jj4 * 4) * 4);
        LDS128(*(uint4*)&fp, fT   + (uint32_t)(r * TPAD + jj4 * 4) * 4);
        float4 h4 = *((const float4*)(hin + row * H_DIM + jbase) + jj4);

        float4 tv, yv;
        float s = 0.f, q = 0.f;
        {
            const float* ptp = &tp.x; const float* pfp = &fp.x;
            const float* ph = &h4.x; const float* pbt = &bt4.x; const float* pbi = &bi4.x;
            float* ptv = &tv.x; float* pyv = &yv.x;
#pragma unroll
            for (int c = 0; c < 4; c++) {
                float tau = 0.5f + 4.5f / (1.0f + __expf(-(ptp[c] + pbt[c])));
                float f   = tanhf(pfp[c] + pbi[c]);
                float yy  = ph[c] + 0.1f * (f - ph[c]) / tau;
                ptv[c] = tau; pyv[c] = yy;
                s += yy; q += yy * yy;
            }
        }
        *((float4*)(out_tau + row * H_DIM + jbase) + jj4) = tv;
        *((float4*)(g_Y + row * H_DIM + jbase) + jj4) = yv;

        // reduce s,q across the 16 lanes of this half-warp
        s += __shfl_xor_sync(0xffffffffu, s, 1);
        q += __shfl_xor_sync(0xffffffffu, q, 1);
        s += __shfl_xor_sync(0xffffffffu, s, 2);
        q += __shfl_xor_sync(0xffffffffu, q, 2);
        s += __shfl_xor_sync(0xffffffffu, s, 4);
        q += __shfl_xor_sync(0xffffffffu, q, 4);
        s += __shfl_xor_sync(0xffffffffu, s, 8);
        q += __shfl_xor_sync(0xffffffffu, q, 8);
        if (jj4 == 0)
            g_Spart[row * 8 + bn] = make_float2(s, q);
    }
}

// ---------------------------------------------------------------------------
// Finalize: reduce 8 LN partials per row, normalize y -> out_h. 2 rows/block.
// ---------------------------------------------------------------------------
__global__ __launch_bounds__(256)
void finalize_kernel(const float* __restrict__ gamma, const float* __restrict__ beta,
                     float* __restrict__ out_h) {
    const int tid = threadIdx.x;
    const int r   = tid >> 7;
    const int t   = tid & 127;
    const size_t row = (size_t)blockIdx.x * 2 + r;
    const int w = tid >> 5;
    const int lane = tid & 31;

    __shared__ float2 mv[2];
    if (w == 0 || w == 4) {
        size_t rr = (size_t)blockIdx.x * 2 + (w >> 2);
        float2 p = (lane < 8) ? g_Spart[rr * 8 + lane] : make_float2(0.f, 0.f);
        float s = p.x, q = p.y;
#pragma unroll
        for (int off = 4; off > 0; off >>= 1) {
            s += __shfl_xor_sync(0xffffffffu, s, off);
            q += __shfl_xor_sync(0xffffffffu, q, off);
        }
        if (lane == 0) {
            float mu  = s * (1.0f / H_DIM);
            float var = q * (1.0f / H_DIM) - mu * mu;
            mv[w >> 2] = make_float2(mu, rsqrtf(var + 1e-5f));
        }
    }
    __syncthreads();

    float mu  = mv[r].x;
    float inv = mv[r].y;

    float4 y4 = *((const float4*)(g_Y + row * H_DIM) + t);
    float4 g4 = ((const float4*)gamma)[t];
    float4 b4 = ((const float4*)beta)[t];
    float4 oh;
    oh.x = (y4.x - mu) * inv * g4.x + b4.x;
    oh.y = (y4.y - mu) * inv * g4.y + b4.y;
    oh.z = (y4.z - mu) * inv * g4.z + b4.z;
    oh.w = (y4.w - mu) * inv * g4.w + b4.w;
    *((float4*)(out_h + row * H_DIM) + t) = oh;
}

// ---------------------------------------------------------------------------
extern "C" void kernel_launch(void* const* d_in, const int* in_sizes, int n_in,
                              void* d_out, int out_size) {
    const float* x     = (const float*)d_in[0];
    const float* h     = (const float*)d_in[1];
    const float* W_in  = (const float*)d_in[2];
    const float* b_in  = (const float*)d_in[3];
    const float* W_rec = (const float*)d_in[4];
    const float* W_tau = (const float*)d_in[5];
    const float* b_tau = (const float*)d_in[6];
    const float* gamma = (const float*)d_in[7];
    const float* beta  = (const float*)d_in[8];

    const int B = in_sizes[0] / I_DIM;    // 65536

    float* out = (float*)d_out;
    float* out_h   = out;
    float* out_tau = out + (size_t)B * H_DIM;

    pack_w_kernel<<<512, 256>>>(W_in, W_rec, W_tau);
    split_a_kernel<<<B / 16, 256>>>(x, h);

    cudaFuncSetAttribute(gemm_mma_kernel,
                         cudaFuncAttributeMaxDynamicSharedMemorySize,
                         N_STAGES * STAGE_BYTES);
    dim3 ggrid(NTOT / 128, B / 128);      // (8, 512)
    gemm_mma_kernel<<<ggrid, 256, N_STAGES * STAGE_BYTES>>>(h, b_in, b_tau, out_tau);

    finalize_kernel<<<B / 2, 256>>>(gamma, beta, out_h);
}

// round 11
// speedup vs baseline: 1.0531x; 1.0227x over previous
#include <cuda_runtime.h>
#include <cuda_bf16.h>
#include <cstdint>
#include <cmath>

#define I_DIM 512
#define H_DIM 512
#define KTOT  1024
#define NTOT  1024
#define BATCH 65536

// ---------------------------------------------------------------------------
// Device scratch
// A2: u4 index = ((rb*64 + kb)*2 + term)*32 + lane
// W2: u4 index = ((nb*64 + kb)*2 + term)*32 + lane  (cols interleaved: 2j=tau, 2j+1=f)
// ---------------------------------------------------------------------------
__device__ uint4  g_A2[(size_t)4096 * 64 * 2 * 32];      // 256 MB
__device__ uint4  g_W2[(size_t)64 * 64 * 2 * 32];        // 4 MB
__device__ float  g_Y[(size_t)BATCH * H_DIM];            // 128 MB (pre-LN y)
__device__ float2 g_Spart[(size_t)BATCH * 8];            // 4 MB (LN partials, per bn)

__device__ __forceinline__ uint32_t smem_u32(const void* p) {
    uint32_t a;
    asm("{ .reg .u64 t; cvta.to.shared.u64 t, %1; cvt.u32.u64 %0, t; }"
        : "=r"(a) : "l"(p));
    return a;
}
__device__ __forceinline__ uint32_t pack_bf2(float a, float b) {
    __nv_bfloat16 ha = __float2bfloat16(a);
    __nv_bfloat16 hb = __float2bfloat16(b);
    return (uint32_t)__bfloat16_as_ushort(ha) |
           ((uint32_t)__bfloat16_as_ushort(hb) << 16);
}
__device__ __forceinline__ float bf_hi(float v) {
    return __bfloat162float(__float2bfloat16(v));
}
__device__ __forceinline__ void mma16816(float* c, const uint4& a,
                                         uint32_t b0, uint32_t b1) {
    asm volatile(
        "mma.sync.aligned.m16n8k16.row.col.f32.bf16.bf16.f32 "
        "{%0,%1,%2,%3}, {%4,%5,%6,%7}, {%8,%9}, {%0,%1,%2,%3};"
        : "+f"(c[0]), "+f"(c[1]), "+f"(c[2]), "+f"(c[3])
        : "r"(a.x), "r"(a.y), "r"(a.z), "r"(a.w), "r"(b0), "r"(b1));
}
#define CP_ASYNC16(dst, src) \
    asm volatile("cp.async.cg.shared.global [%0], [%1], 16;" \
                 :: "r"(dst), "l"(src) : "memory")
#define CP_COMMIT() asm volatile("cp.async.commit_group;" ::: "memory")
#define CP_WAIT1()  asm volatile("cp.async.wait_group 1;" ::: "memory")
#define CP_WAIT0()  asm volatile("cp.async.wait_group 0;" ::: "memory")
#define LDS128(v, addr) \
    asm volatile("ld.shared.v4.u32 {%0,%1,%2,%3}, [%4];" \
        : "=r"((v).x), "=r"((v).y), "=r"((v).z), "=r"((v).w) : "r"(addr))

// ---------------------------------------------------------------------------
// Pack W (interleaved columns: packed col c -> j=c>>1; even=tau, odd=f).
// ---------------------------------------------------------------------------
__device__ __forceinline__ float w_at2(const float* W_in, const float* W_rec,
                                       const float* W_tau, int c, int k) {
    int j = c >> 1;
    if ((c & 1) == 0) return W_tau[j * KTOT + k];
    return (k < I_DIM) ? W_in[j * I_DIM + k] : W_rec[j * H_DIM + (k - I_DIM)];
}

__global__ void pack_w_kernel(const float* __restrict__ W_in,
                              const float* __restrict__ W_rec,
                              const float* __restrict__ W_tau) {
    int t = blockIdx.x * blockDim.x + threadIdx.x;
    int lane = t & 31;
    int idx = t >> 5;
    int kb = idx & 63;
    int nb = idx >> 6;

    int n0 = nb * 16 + (lane >> 2);
    int k0 = kb * 16 + (lane & 3) * 2;

    float v[8];
    v[0] = w_at2(W_in, W_rec, W_tau, n0,     k0);
    v[1] = w_at2(W_in, W_rec, W_tau, n0,     k0 + 1);
    v[2] = w_at2(W_in, W_rec, W_tau, n0,     k0 + 8);
    v[3] = w_at2(W_in, W_rec, W_tau, n0,     k0 + 9);
    v[4] = w_at2(W_in, W_rec, W_tau, n0 + 8, k0);
    v[5] = w_at2(W_in, W_rec, W_tau, n0 + 8, k0 + 1);
    v[6] = w_at2(W_in, W_rec, W_tau, n0 + 8, k0 + 8);
    v[7] = w_at2(W_in, W_rec, W_tau, n0 + 8, k0 + 9);

    uint4 hi, lo;
    hi.x = pack_bf2(v[0], v[1]); hi.y = pack_bf2(v[2], v[3]);
    hi.z = pack_bf2(v[4], v[5]); hi.w = pack_bf2(v[6], v[7]);
    lo.x = pack_bf2(v[0] - bf_hi(v[0]), v[1] - bf_hi(v[1]));
    lo.y = pack_bf2(v[2] - bf_hi(v[2]), v[3] - bf_hi(v[3]));
    lo.z = pack_bf2(v[4] - bf_hi(v[4]), v[5] - bf_hi(v[5]));
    lo.w = pack_bf2(v[6] - bf_hi(v[6]), v[7] - bf_hi(v[7]));

    size_t base = ((size_t)(nb * 64 + kb) * 2) * 32 + lane;
    g_W2[base]      = hi;
    g_W2[base + 32] = lo;
}

// ---------------------------------------------------------------------------
// Split A = [x | h] into fragment-linear hi/lo bf16 tiles.
// ---------------------------------------------------------------------------
__global__ __launch_bounds__(256)
void split_a_kernel(const float* __restrict__ x, const float* __restrict__ h) {
    const int rb = blockIdx.x;
    const int tid = threadIdx.x;
    const int wid = tid >> 5;
    const int lane = tid & 31;

    const int r0 = lane >> 2;
    const int cq = (lane & 3) * 2;
    const size_t rowA = (size_t)rb * 16 + r0;
    const size_t rowB = rowA + 8;

#pragma unroll
    for (int j = 0; j < 8; j++) {
        int kb = wid * 8 + j;
        int kg = kb * 16 + cq;
        const float* srcA;
        const float* srcB;
        if (kb < 32) { srcA = x + rowA * I_DIM + kg;          srcB = x + rowB * I_DIM + kg; }
        else         { srcA = h + rowA * H_DIM + (kg - 512);  srcB = h + rowB * H_DIM + (kg - 512); }

        float a0 = srcA[0], a1 = srcA[1], a2 = srcA[8], a3 = srcA[9];
        float b0 = srcB[0], b1 = srcB[1], b2 = srcB[8], b3 = srcB[9];

        uint4 hi, lo;
        hi.x = pack_bf2(a0, a1); hi.y = pack_bf2(b0, b1);
        hi.z = pack_bf2(a2, a3); hi.w = pack_bf2(b2, b3);
        lo.x = pack_bf2(a0 - bf_hi(a0), a1 - bf_hi(a1));
        lo.y = pack_bf2(b0 - bf_hi(b0), b1 - bf_hi(b1));
        lo.z = pack_bf2(a2 - bf_hi(a2), a3 - bf_hi(a3));
        lo.w = pack_bf2(b2 - bf_hi(b2), b3 - bf_hi(b3));

        size_t base = ((size_t)(rb * 64 + kb) * 2) * 32 + lane;
        g_A2[base]      = hi;
        g_A2[base + 32] = lo;
    }
}

// ---------------------------------------------------------------------------
// GEMM + smem-staged fused epilogue (R10) with batched h prefetch in the tail.
// ---------------------------------------------------------------------------
#define STAGE_BYTES 32768
#define N_STAGES 3
#define TPAD 68

__global__ __launch_bounds__(256)
void gemm_mma_kernel(const float* __restrict__ hin,
                     const float* __restrict__ b_in,
                     const float* __restrict__ b_tau,
                     float* __restrict__ out_tau) {
    extern __shared__ char smem[];
    const uint32_t sbase = smem_u32(smem);

    const int tid  = threadIdx.x;
    const int wid  = tid >> 5;
    const int lane = tid & 31;
    const int bn = blockIdx.x;            // 0..7
    const int bm = blockIdx.y;            // 0..511
    const int wm = wid & 1;
    const int wn = wid >> 1;

    uint32_t soff[8];
    const uint4* gptr[8];
#pragma unroll
    for (int j = 0; j < 8; j++) {
        int c = tid + j * 256;
        int cl   = c & 31;
        int blk  = (c >> 5) & 7;
        int term = (c >> 8) & 1;
        int kb   = (c >> 9) & 1;
        if (c < 1024) {
            int rb = bm * 8 + blk;
            gptr[j] = g_A2 + (((size_t)(rb * 64 + kb) * 2 + term) * 32 + cl);
        } else {
            int nb = bn * 8 + blk;
            gptr[j] = g_W2 + (((size_t)(nb * 64 + kb) * 2 + term) * 32 + cl);
        }
        soff[j] = (uint32_t)(c * 16);
    }

    float acc[4][4][4];
#pragma unroll
    for (int a = 0; a < 4; a++)
#pragma unroll
        for (int b = 0; b < 4; b++)
#pragma unroll
            for (int d = 0; d < 4; d++) acc[a][b][d] = 0.f;

#pragma unroll
    for (int s = 0; s < 2; s++) {
#pragma unroll
        for (int j = 0; j < 8; j++)
            CP_ASYNC16(sbase + s * STAGE_BYTES + soff[j], gptr[j] + (size_t)s * 128);
        CP_COMMIT();
    }

    const int mbB = wm * 4;
    const int nbB = wn * 2;

    for (int i = 0; i < 32; i++) {
        CP_WAIT1();
        __syncthreads();

        if (i + 2 < 32) {
            uint32_t sb = sbase + ((i + 2) % N_STAGES) * STAGE_BYTES;
#pragma unroll
            for (int j = 0; j < 8; j++)
                CP_ASYNC16(sb + soff[j], gptr[j] + (size_t)(i + 2) * 128);
        }
        CP_COMMIT();

        const uint32_t st = sbase + (i % N_STAGES) * STAGE_BYTES;
#pragma unroll
        for (int kb = 0; kb < 2; kb++) {
            uint4 ah[4], al[4], bh[2], bl[2];
#pragma unroll
            for (int mb = 0; mb < 4; mb++) {
                uint32_t ahi = st + ((kb * 2 + 0) * 8 + mbB + mb) * 512 + lane * 16;
                uint32_t alo = st + ((kb * 2 + 1) * 8 + mbB + mb) * 512 + lane * 16;
                LDS128(ah[mb], ahi);
                LDS128(al[mb], alo);
            }
#pragma unroll
            for (int p = 0; p < 2; p++) {
                uint32_t bhi = st + 16384 + ((kb * 2 + 0) * 8 + nbB + p) * 512 + lane * 16;
                uint32_t blo = st + 16384 + ((kb * 2 + 1) * 8 + nbB + p) * 512 + lane * 16;
                LDS128(bh[p], bhi);
                LDS128(bl[p], blo);
            }
#pragma unroll
            for (int term = 0; term < 3; term++) {
#pragma unroll
                for (int mt = 0; mt < 4; mt++) {
#pragma unroll
                    for (int nt = 0; nt < 4; nt++) {
                        const uint4& A = (term == 2) ? al[mt] : ah[mt];
                        const uint4& B = (term == 1) ? bl[nt >> 1] : bh[nt >> 1];
                        uint32_t b0 = (nt & 1) ? B.z : B.x;
                        uint32_t b1 = (nt & 1) ? B.w : B.y;
                        mma16816(acc[mt][nt], A, b0, b1);
                    }
                }
            }
        }
    }

    // ---- tail: drain pipeline, then reuse smem for staging ----
    CP_WAIT0();
    __syncthreads();

    const uint32_t tauT = sbase;                  // [128][68] float
    const uint32_t fT   = sbase + 128 * TPAD * 4; // [128][68] float
    const int g  = lane >> 2;
    const int tg = lane & 3;

    // Phase 1: scatter raw pre-activations to smem
#pragma unroll
    for (int mt = 0; mt < 4; mt++) {
        int r0 = wm * 64 + mt * 16 + g;
        int r1 = r0 + 8;
#pragma unroll
        for (int nt = 0; nt < 4; nt++) {
            int jj = wn * 16 + nt * 4 + tg;
            asm volatile("st.shared.f32 [%0], %1;" :: "r"(tauT + (uint32_t)(r0 * TPAD + jj) * 4), "f"(acc[mt][nt][0]) : "memory");
            asm volatile("st.shared.f32 [%0], %1;" :: "r"(fT   + (uint32_t)(r0 * TPAD + jj) * 4), "f"(acc[mt][nt][1]) : "memory");
            asm volatile("st.shared.f32 [%0], %1;" :: "r"(tauT + (uint32_t)(r1 * TPAD + jj) * 4), "f"(acc[mt][nt][2]) : "memory");
            asm volatile("st.shared.f32 [%0], %1;" :: "r"(fT   + (uint32_t)(r1 * TPAD + jj) * 4), "f"(acc[mt][nt][3]) : "memory");
        }
    }
    __syncthreads();

    // Phase 2: coalesced writeout, h prefetched in batches of 4 (MLP=4).
    const int jj4 = tid & 15;
    const int rgrp = tid >> 4;
    const int jbase = bn * 64;
    const float4 bt4 = ((const float4*)b_tau)[jbase / 4 + jj4];
    const float4 bi4 = ((const float4*)b_in)[jbase / 4 + jj4];

#pragma unroll
    for (int half = 0; half < 2; half++) {
        float4 h4s[4];
#pragma unroll
        for (int u = 0; u < 4; u++) {
            int r = rgrp + (half * 4 + u) * 16;
            size_t row = (size_t)bm * 128 + r;
            h4s[u] = *((const float4*)(hin + row * H_DIM + jbase) + jj4);
        }
#pragma unroll
        for (int u = 0; u < 4; u++) {
            int r = rgrp + (half * 4 + u) * 16;
            size_t row = (size_t)bm * 128 + r;

            float4 tp, fp;
            LDS128(*(uint4*)&tp, tauT + (uint32_t)(r * TPAD + jj4 * 4) * 4);
            LDS128(*(uint4*)&fp, fT   + (uint32_t)(r * TPAD + jj4 * 4) * 4);
            float4 h4 = h4s[u];

            float4 tv, yv;
            float s = 0.f, q = 0.f;
            {
                const float* ptp = &tp.x; const float* pfp = &fp.x;
                const float* ph = &h4.x; const float* pbt = &bt4.x; const float* pbi = &bi4.x;
                float* ptv = &tv.x; float* pyv = &yv.x;
#pragma unroll
                for (int c = 0; c < 4; c++) {
                    float tau = 0.5f + 4.5f / (1.0f + __expf(-(ptp[c] + pbt[c])));
                    float f   = tanhf(pfp[c] + pbi[c]);
                    float yy  = ph[c] + 0.1f * (f - ph[c]) / tau;
                    ptv[c] = tau; pyv[c] = yy;
                    s += yy; q += yy * yy;
                }
            }
            *((float4*)(out_tau + row * H_DIM + jbase) + jj4) = tv;
            *((float4*)(g_Y + row * H_DIM + jbase) + jj4) = yv;

            s += __shfl_xor_sync(0xffffffffu, s, 1);
            q += __shfl_xor_sync(0xffffffffu, q, 1);
            s += __shfl_xor_sync(0xffffffffu, s, 2);
            q += __shfl_xor_sync(0xffffffffu, q, 2);
            s += __shfl_xor_sync(0xffffffffu, s, 4);
            q += __shfl_xor_sync(0xffffffffu, q, 4);
            s += __shfl_xor_sync(0xffffffffu, s, 8);
            q += __shfl_xor_sync(0xffffffffu, q, 8);
            if (jj4 == 0)
                g_Spart[row * 8 + bn] = make_float2(s, q);
        }
    }
}

// ---------------------------------------------------------------------------
// Finalize: 4 rows / 256-thread block, 2 float4 per thread, y-loads issued
// before the partial-reduction barrier (latency overlap).
// ---------------------------------------------------------------------------
__global__ __launch_bounds__(256)
void finalize_kernel(const float* __restrict__ gamma, const float* __restrict__ beta,
                     float* __restrict__ out_h) {
    const int tid = threadIdx.x;
    const size_t row0 = (size_t)blockIdx.x * 4;
    const int r = tid >> 6;           // 0..3
    const int t = tid & 63;           // f4 indices t and t+64
    const size_t row = row0 + r;

    // issue y loads early (independent of the reduction)
    float4 ya = *((const float4*)(g_Y + row * H_DIM) + t);
    float4 yb = *((const float4*)(g_Y + row * H_DIM) + t + 64);

    __shared__ float2 mv[4];
    if (tid < 32) {
        int rr = tid >> 3, part = tid & 7;
        float2 p = g_Spart[(row0 + rr) * 8 + part];
        float s = p.x, q = p.y;
        s += __shfl_xor_sync(0xffffffffu, s, 1);
        q += __shfl_xor_sync(0xffffffffu, q, 1);
        s += __shfl_xor_sync(0xffffffffu, s, 2);
        q += __shfl_xor_sync(0xffffffffu, q, 2);
        s += __shfl_xor_sync(0xffffffffu, s, 4);
        q += __shfl_xor_sync(0xffffffffu, q, 4);
        if (part == 0) {
            float mu  = s * (1.0f / H_DIM);
            float var = q * (1.0f / H_DIM) - mu * mu;
            mv[rr] = make_float2(mu, rsqrtf(var + 1e-5f));
        }
    }
    __syncthreads();

    float mu  = mv[r].x;
    float inv = mv[r].y;

    float4 ga = ((const float4*)gamma)[t];
    float4 gb = ((const float4*)gamma)[t + 64];
    float4 ba = ((const float4*)beta)[t];
    float4 bb = ((const float4*)beta)[t + 64];

    float4 oa, ob;
    oa.x = (ya.x - mu) * inv * ga.x + ba.x;
    oa.y = (ya.y - mu) * inv * ga.y + ba.y;
    oa.z = (ya.z - mu) * inv * ga.z + ba.z;
    oa.w = (ya.w - mu) * inv * ga.w + ba.w;
    ob.x = (yb.x - mu) * inv * gb.x + bb.x;
    ob.y = (yb.y - mu) * inv * gb.y + bb.y;
    ob.z = (yb.z - mu) * inv * gb.z + bb.z;
    ob.w = (yb.w - mu) * inv * gb.w + bb.w;

    *((float4*)(out_h + row * H_DIM) + t) = oa;
    *((float4*)(out_h + row * H_DIM) + t + 64) = ob;
}

// ---------------------------------------------------------------------------
extern "C" void kernel_launch(void* const* d_in, const int* in_sizes, int n_in,
                              void* d_out, int out_size) {
    const float* x     = (const float*)d_in[0];
    const float* h     = (const float*)d_in[1];
    const float* W_in  = (const float*)d_in[2];
    const float* b_in  = (const float*)d_in[3];
    const float* W_rec = (const float*)d_in[4];
    const float* W_tau = (const float*)d_in[5];
    const float* b_tau = (const float*)d_in[6];
    const float* gamma = (const float*)d_in[7];
    const float* beta  = (const float*)d_in[8];

    const int B = in_sizes[0] / I_DIM;    // 65536

    float* out = (float*)d_out;
    float* out_h   = out;
    float* out_tau = out + (size_t)B * H_DIM;

    pack_w_kernel<<<512, 256>>>(W_in, W_rec, W_tau);
    split_a_kernel<<<B / 16, 256>>>(x, h);

    cudaFuncSetAttribute(gemm_mma_kernel,
                         cudaFuncAttributeMaxDynamicSharedMemorySize,
                         N_STAGES * STAGE_BYTES);
    dim3 ggrid(NTOT / 128, B / 128);      // (8, 512)
    gemm_mma_kernel<<<ggrid, 256, N_STAGES * STAGE_BYTES>>>(h, b_in, b_tau, out_tau);

    finalize_kernel<<<B / 4, 256>>>(gamma, beta, out_h);
}